// round 13
// baseline (speedup 1.0000x reference)
#include <cuda_runtime.h>
#include <cuda_bf16.h>
#include <math.h>
#include <stdint.h>

// Shapes (fixed)
#define BB   512
#define MM   128
#define N3   381
#define CIN  200
#define CP1  256
#define H1   512
#define H2   512
#define FF   256

// Activations
__device__ __align__(16) float g_buf1[(size_t)BB * MM * H1];
__device__ __align__(16) float g_buf2[(size_t)BB * MM * H2];
__device__ __align__(16) __nv_bfloat16 g_tHi[(size_t)BB * MM * CP1], g_tLo[(size_t)BB * MM * CP1];
__device__ __align__(16) __nv_bfloat16 g_aHi[(size_t)BB * MM * H1],  g_aLo[(size_t)BB * MM * H1];
// Weights, k' = k3*Cp + c order, bf16 hi/lo
__device__ __align__(16) __nv_bfloat16 g_w1_hi[H1 * 3 * CP1], g_w1_lo[H1 * 3 * CP1];
__device__ __align__(16) __nv_bfloat16 g_w2_hi[H2 * 3 * H1],  g_w2_lo[H2 * 3 * H1];
__device__ __align__(16) __nv_bfloat16 g_w3_hi[FF * 3 * H2],  g_w3_lo[FF * 3 * H2];
__device__ float2 g_part[BB * 4];
__device__ float2 g_stats1[BB];
__device__ float2 g_stats2[BB];

#define SW128(o) ((o) ^ (((o) >> 3) & 0x70))

__device__ __forceinline__ uint32_t smem_u32(const void* p) {
    uint32_t a;
    asm("{ .reg .u64 t; cvta.to.shared.u64 t, %1; cvt.u32.u64 %0, t; }" : "=r"(a) : "l"(p));
    return a;
}
__device__ __forceinline__ void cp_async16(uint32_t dst, const void* src, int src_sz) {
    asm volatile("cp.async.cg.shared.global [%0], [%1], 16, %2;"
                 :: "r"(dst), "l"(src), "r"(src_sz) : "memory");
}
__device__ __forceinline__ void cp_commit() {
    asm volatile("cp.async.commit_group;" ::: "memory");
}
template<int N>
__device__ __forceinline__ void cp_wait() {
    asm volatile("cp.async.wait_group %0;" :: "n"(N) : "memory");
}
__device__ __forceinline__ void ldmx4(uint32_t* r, uint32_t addr) {
    asm volatile("ldmatrix.sync.aligned.m8n8.x4.shared.b16 {%0,%1,%2,%3}, [%4];"
                 : "=r"(r[0]), "=r"(r[1]), "=r"(r[2]), "=r"(r[3]) : "r"(addr));
}
__device__ __forceinline__ void mma16816(float* c, const uint32_t* a, uint32_t b0, uint32_t b1) {
    asm volatile(
        "mma.sync.aligned.m16n8k16.row.col.f32.bf16.bf16.f32 "
        "{%0,%1,%2,%3},{%4,%5,%6,%7},{%8,%9},{%0,%1,%2,%3};"
        : "+f"(c[0]), "+f"(c[1]), "+f"(c[2]), "+f"(c[3])
        : "r"(a[0]), "r"(a[1]), "r"(a[2]), "r"(a[3]), "r"(b0), "r"(b1));
}
__device__ __forceinline__ void split_bf16(float x, unsigned short& h, unsigned short& l) {
    __nv_bfloat16 hh = __float2bfloat16_rn(x);
    h = __bfloat16_as_ushort(hh);
    l = __bfloat16_as_ushort(__float2bfloat16_rn(x - __bfloat162float(hh)));
}

// ---------------------------------------------------------------------------
// trees [B][CIN][128] -> hi/lo bf16 [B][128][CP1]
// ---------------------------------------------------------------------------
__global__ __launch_bounds__(256) void transpose_split(
    const float* __restrict__ in,
    __nv_bfloat16* __restrict__ ohi, __nv_bfloat16* __restrict__ olo)
{
    __shared__ float tile[32][33];
    const int b = blockIdx.z;
    const int c0 = blockIdx.x * 32, m0 = blockIdx.y * 32;
    const int tx = threadIdx.x & 31, ty = threadIdx.x >> 5;
    const float* ib = in + (size_t)b * CIN * MM;
    #pragma unroll
    for (int i = 0; i < 4; i++) {
        int c = c0 + ty + i * 8;
        tile[ty + i * 8][tx] = (c < CIN) ? ib[c * MM + m0 + tx] : 0.f;
    }
    __syncthreads();
    #pragma unroll
    for (int i = 0; i < 4; i++) {
        int m = m0 + ty + i * 8;
        float v = tile[tx][ty + i * 8];
        unsigned short h, l;
        split_bf16(v, h, l);
        size_t o = (size_t)b * MM * CP1 + (size_t)m * CP1 + c0 + tx;
        ohi[o] = __ushort_as_bfloat16(h);
        olo[o] = __ushort_as_bfloat16(l);
    }
}

// ---------------------------------------------------------------------------
// W[o][c*3+k3] -> hi/lo bf16 at [o][k3*Cp + c]
// ---------------------------------------------------------------------------
__global__ void wprep(const float* __restrict__ w, __nv_bfloat16* __restrict__ hi,
                      __nv_bfloat16* __restrict__ lo, int O, int C, int Cp)
{
    int i = blockIdx.x * 256 + threadIdx.x;
    int KT = 3 * Cp;
    if (i >= O * KT) return;
    int o = i / KT, kp = i - o * KT;
    int k3 = kp / Cp, c = kp - k3 * Cp;
    float v = (c < C) ? w[o * C * 3 + c * 3 + k3] : 0.f;
    unsigned short h, l;
    split_bf16(v, h, l);
    hi[i] = __ushort_as_bfloat16(h);
    lo[i] = __ushort_as_bfloat16(l);
}

// ---------------------------------------------------------------------------
// LN(+ReLU) + bf16 split
// ---------------------------------------------------------------------------
__global__ __launch_bounds__(512) void ln_split(
    const float* __restrict__ in, const float2* __restrict__ stats,
    __nv_bfloat16* __restrict__ ohi, __nv_bfloat16* __restrict__ olo, int per)
{
    const int b = blockIdx.x;
    const float2 st = stats[b];
    const float mean = st.x, inv = st.y;
    const float4* ip = (const float4*)(in + (size_t)b * per);
    uint2* hp = (uint2*)(ohi + (size_t)b * per);
    uint2* lp = (uint2*)(olo + (size_t)b * per);
    const int n4 = per / 4;
    for (int i = threadIdx.x; i < n4; i += 512) {
        float4 v = ip[i];
        float x0 = fmaxf((v.x - mean) * inv, 0.f);
        float x1 = fmaxf((v.y - mean) * inv, 0.f);
        float x2 = fmaxf((v.z - mean) * inv, 0.f);
        float x3 = fmaxf((v.w - mean) * inv, 0.f);
        unsigned short h0, l0, h1, l1, h2, l2, h3, l3;
        split_bf16(x0, h0, l0); split_bf16(x1, h1, l1);
        split_bf16(x2, h2, l2); split_bf16(x3, h3, l3);
        hp[i] = make_uint2((uint32_t)h0 | ((uint32_t)h1 << 16),
                           (uint32_t)h2 | ((uint32_t)h3 << 16));
        lp[i] = make_uint2((uint32_t)l0 | ((uint32_t)l1 << 16),
                           (uint32_t)l2 | ((uint32_t)l3 << 16));
    }
}

// ---------------------------------------------------------------------------
// Conv: 256 threads, 8 warps (2x4 grid, 64x32 warp tiles), cp.async staging,
// depth-2 pipeline, pre-split bf16 hi/lo inputs.
// ---------------------------------------------------------------------------
#define STG 65536
#define DYN_SMEM (2 * STG)

template<int O, int Cp, bool STATS>
__global__ __launch_bounds__(256, 1) void conv_mma(
    const __nv_bfloat16* __restrict__ Xhi,   // [B][128][Cp]
    const __nv_bfloat16* __restrict__ Xlo,
    const int*   __restrict__ idx,
    const __nv_bfloat16* __restrict__ whi,   // [O][3*Cp]
    const __nv_bfloat16* __restrict__ wlo,
    const float* __restrict__ bias,
    float2* __restrict__ part_out,
    float* __restrict__ out)                 // [B][128][O]
{
    const int KT = 3 * Cp;
    const int NCH = Cp / 64;
    const int NC = 3 * NCH;

    extern __shared__ char base[];
    __shared__ int idxs[384];
    __shared__ float sbias[128];
    __shared__ float redS[8], redS2[8];

    const int b  = blockIdx.y;
    const int o0 = blockIdx.x * 128;
    const int t  = threadIdx.x;
    const int wid = t >> 5, lane = t & 31;

    for (int i = t; i < 384; i += 256) idxs[i] = (i < N3) ? idx[b * N3 + i] : 0;
    if (t < 128) sbias[t] = bias[o0 + t];
    __syncthreads();

    const __nv_bfloat16* XhB = Xhi + (size_t)b * MM * Cp;
    const __nv_bfloat16* XlB = Xlo + (size_t)b * MM * Cp;
    const uint32_t sbase = smem_u32(base);

    auto issue = [&](int ch, int s) {
        const int k3 = ch / NCH, c0 = (ch - k3 * NCH) * 64;
        const uint32_t st = sbase + s * STG;
        // A: 128 rows x 8 parts, hi+lo (gathered; row 127 zero-filled)
        #pragma unroll
        for (int i = 0; i < 4; i++) {
            int e = i * 256 + t, r = e >> 3, part = e & 7;
            uint32_t d = st + SW128(r * 128 + part * 16);
            int sz = (r < 127) ? 16 : 0;
            size_t g = (size_t)idxs[3 * r + k3] * Cp + c0 + part * 8;
            cp_async16(d,         XhB + g, sz);
            cp_async16(d + 16384, XlB + g, sz);
        }
        // B: 128 rows x 8 parts, hi+lo
        #pragma unroll
        for (int i = 0; i < 4; i++) {
            int e = i * 256 + t, r = e >> 3, part = e & 7;
            uint32_t d = st + 32768 + SW128(r * 128 + part * 16);
            size_t g = (size_t)(o0 + r) * KT + k3 * Cp + c0 + part * 8;
            cp_async16(d,         whi + g, 16);
            cp_async16(d + 16384, wlo + g, 16);
        }
        cp_commit();
    };

    const int m0 = (wid & 1) * 64;   // 2 M bands of 64
    const int n0 = (wid >> 1) * 32;  // 4 N bands of 32

    float acc[4][4][4];
    #pragma unroll
    for (int i = 0; i < 4; i++)
        #pragma unroll
        for (int j = 0; j < 4; j++)
            #pragma unroll
            for (int q = 0; q < 4; q++) acc[i][j][q] = 0.f;

    issue(0, 0);
    if (NC > 1) issue(1, 1);

    for (int ch = 0; ch < NC; ch++) {
        const int s = ch & 1;
        if (ch + 1 < NC) cp_wait<1>(); else cp_wait<0>();
        __syncthreads();

        const uint32_t tA_hi = sbase + s * STG;
        const uint32_t tA_lo = tA_hi + 16384;
        const uint32_t tB_hi = tA_hi + 32768;
        const uint32_t tB_lo = tA_hi + 49152;
        #pragma unroll
        for (int ks = 0; ks < 4; ks++) {
            uint32_t ah[4][4], al[4][4];
            const int arow = lane & 15, ahalf = lane >> 4;
            #pragma unroll
            for (int mi = 0; mi < 4; mi++) {
                uint32_t off = SW128((m0 + 16 * mi + arow) * 128 + ks * 32 + ahalf * 16);
                ldmx4(ah[mi], tA_hi + off);
                ldmx4(al[mi], tA_lo + off);
            }
            uint32_t bh[2][4], bl[2][4];
            #pragma unroll
            for (int h = 0; h < 2; h++) {
                uint32_t off = SW128((n0 + lane) * 128 + ks * 32 + h * 16);
                ldmx4(bh[h], tB_hi + off);
                ldmx4(bl[h], tB_lo + off);
            }
            #pragma unroll
            for (int mi = 0; mi < 4; mi++)
                #pragma unroll
                for (int nj = 0; nj < 4; nj++) {
                    mma16816(acc[mi][nj], ah[mi], bh[0][nj], bh[1][nj]);
                    mma16816(acc[mi][nj], ah[mi], bl[0][nj], bl[1][nj]);
                    mma16816(acc[mi][nj], al[mi], bh[0][nj], bh[1][nj]);
                }
        }
        __syncthreads();                 // all warps done reading stage s
        if (ch + 2 < NC) issue(ch + 2, s);
    }

    // ---- epilogue: direct stores (m = r+1, row 0 zeroed) + register stats ----
    float* outB = out + (size_t)b * MM * O + o0;
    if (t < 128) outB[t] = 0.f;

    float s = 0.f, s2 = 0.f;
    #pragma unroll
    for (int mi = 0; mi < 4; mi++) {
        int r_lo = m0 + 16 * mi + (lane >> 2);
        int r_hi = r_lo + 8;
        #pragma unroll
        for (int nj = 0; nj < 4; nj++) {
            int n = n0 + 8 * nj + 2 * (lane & 3);
            float b0 = sbias[n], b1 = sbias[n + 1];
            float v0 = acc[mi][nj][0] + b0, v1 = acc[mi][nj][1] + b1;
            *(float2*)&outB[(size_t)(r_lo + 1) * O + n] = make_float2(v0, v1);
            if (STATS) { s += v0 + v1; s2 += v0 * v0 + v1 * v1; }
            if (r_hi < 127) {
                float v2 = acc[mi][nj][2] + b0, v3 = acc[mi][nj][3] + b1;
                *(float2*)&outB[(size_t)(r_hi + 1) * O + n] = make_float2(v2, v3);
                if (STATS) { s += v2 + v3; s2 += v2 * v2 + v3 * v3; }
            }
        }
    }
    if (STATS) {
        #pragma unroll
        for (int off = 16; off; off >>= 1) {
            s  += __shfl_xor_sync(0xFFFFFFFFu, s,  off);
            s2 += __shfl_xor_sync(0xFFFFFFFFu, s2, off);
        }
        if (lane == 0) { redS[wid] = s; redS2[wid] = s2; }
        __syncthreads();
        if (t == 0) {
            float S = 0.f, S2 = 0.f;
            #pragma unroll
            for (int i = 0; i < 8; i++) { S += redS[i]; S2 += redS2[i]; }
            part_out[b * (O / 128) + blockIdx.x] = make_float2(S, S2);
        }
    }
}

__global__ void finalize_stats(const float2* __restrict__ part, int nOC,
                               float2* __restrict__ stats, float cnt)
{
    int b = blockIdx.x * blockDim.x + threadIdx.x;
    if (b >= BB) return;
    float S = 0.f, S2 = 0.f;
    for (int i = 0; i < nOC; i++) { float2 p = part[b * nOC + i]; S += p.x; S2 += p.y; }
    double mean = (double)S / (double)cnt;
    double var  = ((double)S2 - (double)S * (double)S / (double)cnt) / ((double)cnt - 1.0);
    if (var < 0.0) var = 0.0;
    stats[b] = make_float2((float)mean, 1.f / ((float)sqrt(var) + 1e-5f));
}

// ---------------------------------------------------------------------------
// Attention head + MLP, emb node-major [B][128][256]
// ---------------------------------------------------------------------------
__global__ __launch_bounds__(256) void head_kernel(
    const float* __restrict__ emb,
    const float* __restrict__ gw1, const float* __restrict__ gb1,
    const float* __restrict__ gw2, const float* __restrict__ gb2,
    const float* __restrict__ rw1, const float* __restrict__ rb1,
    const float* __restrict__ rw2, const float* __restrict__ rb2,
    const float* __restrict__ rw3, const float* __restrict__ rb3,
    float* __restrict__ dout, int write_comb, int write_out)
{
    const int b = blockIdx.x;
    const int t = threadIdx.x;
    const float* E = emb + (size_t)b * MM * FF;

    __shared__ __align__(16) float es[128][33];
    __shared__ __align__(16) float gwT[32][132];
    __shared__ float gates[128];
    __shared__ float red[256];
    __shared__ float attn[128];
    __shared__ __align__(16) float comb[512];
    __shared__ float h1s[128];
    __shared__ float h2s[64];

    const int m  = t >> 1;
    const int h0 = (t & 1) * 64;

    float acc[64];
    #pragma unroll
    for (int j = 0; j < 64; j++) acc[j] = 0.f;

    for (int fc = 0; fc < FF; fc += 32) {
        #pragma unroll
        for (int i = 0; i < 16; i++) {
            int e = i * 256 + t;
            es[e >> 5][e & 31] = E[(e >> 5) * FF + fc + (e & 31)];
        }
        #pragma unroll
        for (int i = 0; i < 16; i++) {
            int e = i * 256 + t;
            gwT[e & 31][e >> 5] = gw1[(e >> 5) * FF + fc + (e & 31)];
        }
        __syncthreads();
        #pragma unroll 2
        for (int fl = 0; fl < 32; fl++) {
            float v = es[m][fl];
            const float* gr = &gwT[fl][h0];
            #pragma unroll
            for (int j = 0; j < 64; j++) acc[j] = fmaf(v, gr[j], acc[j]);
        }
        __syncthreads();
    }

    float g2 = 0.f;
    #pragma unroll
    for (int j = 0; j < 64; j++) {
        float g = acc[j] + gb1[h0 + j];
        g2 = fmaf(fmaxf(g, 0.f), gw2[h0 + j], g2);
    }
    red[t] = g2;
    __syncthreads();
    if ((t & 1) == 0) gates[m] = red[t] + red[t + 1] + gb2[0];
    __syncthreads();

    red[t] = (t < 128) ? gates[t] : -3.0e38f;
    __syncthreads();
    for (int off = 128; off > 0; off >>= 1) {
        if (t < off) red[t] = fmaxf(red[t], red[t + off]);
        __syncthreads();
    }
    float mx = red[0];
    __syncthreads();
    float ev = 0.f;
    if (t < 128) { ev = expf(gates[t] - mx); attn[t] = ev; }
    red[t] = (t < 128) ? ev : 0.f;
    __syncthreads();
    for (int off = 128; off > 0; off >>= 1) {
        if (t < off) red[t] += red[t + off];
        __syncthreads();
    }
    float sinv = 1.f / red[0];
    __syncthreads();
    if (t < 128) attn[t] *= sinv;
    __syncthreads();

    {
        const int f = t;
        float pf = 0.f;
        #pragma unroll 4
        for (int mi = 0; mi < 128; mi++)
            pf = fmaf(attn[mi], E[mi * FF + f], pf);
        comb[256 + f] = pf;
        comb[f]       = E[FF + f];
    }
    __syncthreads();

    if (write_comb) {
        dout[512 + (size_t)b * 512 + t]       = comb[t];
        dout[512 + (size_t)b * 512 + 256 + t] = comb[256 + t];
    }

    if (t < 128) {
        const float4* wr = (const float4*)(rw1 + t * 512);
        const float4* cb = (const float4*)comb;
        float a = rb1[t];
        #pragma unroll 8
        for (int q = 0; q < 128; q++) {
            float4 wv = wr[q];
            float4 cv = cb[q];
            a = fmaf(wv.x, cv.x, a);
            a = fmaf(wv.y, cv.y, a);
            a = fmaf(wv.z, cv.z, a);
            a = fmaf(wv.w, cv.w, a);
        }
        h1s[t] = fmaxf(a, 0.f);
    }
    __syncthreads();
    if (t < 64) {
        const float* wr = rw2 + t * 128;
        float a = rb2[t];
        #pragma unroll 4
        for (int i = 0; i < 128; i++) a = fmaf(h1s[i], wr[i], a);
        h2s[t] = fmaxf(a, 0.f);
    }
    __syncthreads();
    red[t] = (t < 64) ? h2s[t] * rw3[t] : 0.f;
    __syncthreads();
    for (int off = 32; off > 0; off >>= 1) {
        if (t < off) red[t] += red[t + off];
        __syncthreads();
    }
    if (t == 0 && write_out) dout[b] = red[0] + rb3[0];
}

// ---------------------------------------------------------------------------
extern "C" void kernel_launch(void* const* d_in, const int* in_sizes, int n_in,
                              void* d_out, int out_size)
{
    const float* trees   = (const float*)d_in[0];
    const int*   indexes = (const int*)  d_in[1];
    const float* w1  = (const float*)d_in[2];
    const float* b1  = (const float*)d_in[3];
    const float* w2  = (const float*)d_in[4];
    const float* b2  = (const float*)d_in[5];
    const float* w3  = (const float*)d_in[6];
    const float* b3  = (const float*)d_in[7];
    const float* gw1 = (const float*)d_in[8];
    const float* gb1 = (const float*)d_in[9];
    const float* gw2 = (const float*)d_in[10];
    const float* gb2 = (const float*)d_in[11];
    const float* rw1 = (const float*)d_in[12];
    const float* rb1 = (const float*)d_in[13];
    const float* rw2 = (const float*)d_in[14];
    const float* rb2 = (const float*)d_in[15];
    const float* rw3 = (const float*)d_in[16];
    const float* rb3 = (const float*)d_in[17];
    float* out = (float*)d_out;

    float *buf1, *buf2;
    __nv_bfloat16 *tHi, *tLo, *aHi, *aLo;
    __nv_bfloat16 *w1h, *w1l, *w2h, *w2l, *w3h, *w3l;
    float2 *part, *st1, *st2;
    cudaGetSymbolAddress((void**)&buf1, g_buf1);
    cudaGetSymbolAddress((void**)&buf2, g_buf2);
    cudaGetSymbolAddress((void**)&tHi, g_tHi);
    cudaGetSymbolAddress((void**)&tLo, g_tLo);
    cudaGetSymbolAddress((void**)&aHi, g_aHi);
    cudaGetSymbolAddress((void**)&aLo, g_aLo);
    cudaGetSymbolAddress((void**)&w1h, g_w1_hi);
    cudaGetSymbolAddress((void**)&w1l, g_w1_lo);
    cudaGetSymbolAddress((void**)&w2h, g_w2_hi);
    cudaGetSymbolAddress((void**)&w2l, g_w2_lo);
    cudaGetSymbolAddress((void**)&w3h, g_w3_hi);
    cudaGetSymbolAddress((void**)&w3l, g_w3_lo);
    cudaGetSymbolAddress((void**)&part, g_part);
    cudaGetSymbolAddress((void**)&st1, g_stats1);
    cudaGetSymbolAddress((void**)&st2, g_stats2);

    cudaFuncSetAttribute(conv_mma<H1, CP1, true>,
                         cudaFuncAttributeMaxDynamicSharedMemorySize, DYN_SMEM);
    cudaFuncSetAttribute(conv_mma<H2, H1, true>,
                         cudaFuncAttributeMaxDynamicSharedMemorySize, DYN_SMEM);
    cudaFuncSetAttribute(conv_mma<FF, H2, false>,
                         cudaFuncAttributeMaxDynamicSharedMemorySize, DYN_SMEM);

    const long long need_comb = 512LL + (long long)BB * 512LL;
    int write_comb = ((long long)out_size >= need_comb) ? 1 : 0;
    int write_out  = (out_size >= BB) ? 1 : 0;

    transpose_split<<<dim3(CP1 / 32, MM / 32, BB), 256>>>(trees, tHi, tLo);
    wprep<<<(H1 * 3 * CP1 + 255) / 256, 256>>>(w1, w1h, w1l, H1, CIN, CP1);
    wprep<<<(H2 * 3 * H1 + 255) / 256, 256>>>(w2, w2h, w2l, H2, H1, H1);
    wprep<<<(FF * 3 * H2 + 255) / 256, 256>>>(w3, w3h, w3l, FF, H2, H2);

    conv_mma<H1, CP1, true><<<dim3(H1 / 128, BB), 256, DYN_SMEM>>>(
        tHi, tLo, indexes, w1h, w1l, b1, part, buf1);
    finalize_stats<<<(BB + 127) / 128, 128>>>(part, H1 / 128, st1, (float)(H1 * MM));
    ln_split<<<BB, 512>>>(buf1, st1, aHi, aLo, MM * H1);

    conv_mma<H2, H1, true><<<dim3(H2 / 128, BB), 256, DYN_SMEM>>>(
        aHi, aLo, indexes, w2h, w2l, b2, part, buf2);
    finalize_stats<<<(BB + 127) / 128, 128>>>(part, H2 / 128, st2, (float)(H2 * MM));
    ln_split<<<BB, 512>>>(buf2, st2, aHi, aLo, MM * H2);

    conv_mma<FF, H2, false><<<dim3(FF / 128, BB), 256, DYN_SMEM>>>(
        aHi, aLo, indexes, w3h, w3l, b3, nullptr, buf1);

    head_kernel<<<BB, 256>>>(buf1, gw1, gb1, gw2, gb2,
                             rw1, rb1, rw2, rb2, rw3, rb3, out,
                             write_comb, write_out);
}

// round 14
// speedup vs baseline: 1.1073x; 1.1073x over previous
#include <cuda_runtime.h>
#include <cuda_bf16.h>
#include <math.h>
#include <stdint.h>

// Shapes (fixed)
#define BB   512
#define MM   128
#define N3   381
#define CIN  200
#define CP1  256
#define H1   512
#define H2   512
#define FF   256

// Activations
__device__ __align__(16) float g_buf1[(size_t)BB * MM * H1];
__device__ __align__(16) float g_buf2[(size_t)BB * MM * H2];
__device__ __align__(16) __nv_bfloat16 g_tHi[(size_t)BB * MM * CP1], g_tLo[(size_t)BB * MM * CP1];
__device__ __align__(16) __nv_bfloat16 g_aHi[(size_t)BB * MM * H1],  g_aLo[(size_t)BB * MM * H1];
// Weights, k' = k3*Cp + c order, bf16 hi/lo
__device__ __align__(16) __nv_bfloat16 g_w1_hi[H1 * 3 * CP1], g_w1_lo[H1 * 3 * CP1];
__device__ __align__(16) __nv_bfloat16 g_w2_hi[H2 * 3 * H1],  g_w2_lo[H2 * 3 * H1];
__device__ __align__(16) __nv_bfloat16 g_w3_hi[FF * 3 * H2],  g_w3_lo[FF * 3 * H2];
__device__ float2 g_part[BB * 8];
__device__ float2 g_stats1[BB];
__device__ float2 g_stats2[BB];

#define SW128(o) ((o) ^ (((o) >> 3) & 0x70))

__device__ __forceinline__ uint32_t smem_u32(const void* p) {
    uint32_t a;
    asm("{ .reg .u64 t; cvta.to.shared.u64 t, %1; cvt.u32.u64 %0, t; }" : "=r"(a) : "l"(p));
    return a;
}
__device__ __forceinline__ void cp_async16(uint32_t dst, const void* src, int src_sz) {
    asm volatile("cp.async.cg.shared.global [%0], [%1], 16, %2;"
                 :: "r"(dst), "l"(src), "r"(src_sz) : "memory");
}
__device__ __forceinline__ void cp_commit() {
    asm volatile("cp.async.commit_group;" ::: "memory");
}
template<int N>
__device__ __forceinline__ void cp_wait() {
    asm volatile("cp.async.wait_group %0;" :: "n"(N) : "memory");
}
__device__ __forceinline__ void ldmx4(uint32_t* r, uint32_t addr) {
    asm volatile("ldmatrix.sync.aligned.m8n8.x4.shared.b16 {%0,%1,%2,%3}, [%4];"
                 : "=r"(r[0]), "=r"(r[1]), "=r"(r[2]), "=r"(r[3]) : "r"(addr));
}
__device__ __forceinline__ void mma16816(float* c, const uint32_t* a, uint32_t b0, uint32_t b1) {
    asm volatile(
        "mma.sync.aligned.m16n8k16.row.col.f32.bf16.bf16.f32 "
        "{%0,%1,%2,%3},{%4,%5,%6,%7},{%8,%9},{%0,%1,%2,%3};"
        : "+f"(c[0]), "+f"(c[1]), "+f"(c[2]), "+f"(c[3])
        : "r"(a[0]), "r"(a[1]), "r"(a[2]), "r"(a[3]), "r"(b0), "r"(b1));
}
__device__ __forceinline__ void split_bf16(float x, unsigned short& h, unsigned short& l) {
    __nv_bfloat16 hh = __float2bfloat16_rn(x);
    h = __bfloat16_as_ushort(hh);
    l = __bfloat16_as_ushort(__float2bfloat16_rn(x - __bfloat162float(hh)));
}

// ---------------------------------------------------------------------------
// trees [B][CIN][128] -> hi/lo bf16 [B][128][CP1]
// ---------------------------------------------------------------------------
__global__ __launch_bounds__(256) void transpose_split(
    const float* __restrict__ in,
    __nv_bfloat16* __restrict__ ohi, __nv_bfloat16* __restrict__ olo)
{
    __shared__ float tile[32][33];
    const int b = blockIdx.z;
    const int c0 = blockIdx.x * 32, m0 = blockIdx.y * 32;
    const int tx = threadIdx.x & 31, ty = threadIdx.x >> 5;
    const float* ib = in + (size_t)b * CIN * MM;
    #pragma unroll
    for (int i = 0; i < 4; i++) {
        int c = c0 + ty + i * 8;
        tile[ty + i * 8][tx] = (c < CIN) ? ib[c * MM + m0 + tx] : 0.f;
    }
    __syncthreads();
    #pragma unroll
    for (int i = 0; i < 4; i++) {
        int m = m0 + ty + i * 8;
        float v = tile[tx][ty + i * 8];
        unsigned short h, l;
        split_bf16(v, h, l);
        size_t o = (size_t)b * MM * CP1 + (size_t)m * CP1 + c0 + tx;
        ohi[o] = __ushort_as_bfloat16(h);
        olo[o] = __ushort_as_bfloat16(l);
    }
}

// ---------------------------------------------------------------------------
// W[o][c*3+k3] -> hi/lo bf16 at [o][k3*Cp + c]
// ---------------------------------------------------------------------------
__global__ void wprep(const float* __restrict__ w, __nv_bfloat16* __restrict__ hi,
                      __nv_bfloat16* __restrict__ lo, int O, int C, int Cp)
{
    int i = blockIdx.x * 256 + threadIdx.x;
    int KT = 3 * Cp;
    if (i >= O * KT) return;
    int o = i / KT, kp = i - o * KT;
    int k3 = kp / Cp, c = kp - k3 * Cp;
    float v = (c < C) ? w[o * C * 3 + c * 3 + k3] : 0.f;
    unsigned short h, l;
    split_bf16(v, h, l);
    hi[i] = __ushort_as_bfloat16(h);
    lo[i] = __ushort_as_bfloat16(l);
}

// ---------------------------------------------------------------------------
// LN(+ReLU) + bf16 split
// ---------------------------------------------------------------------------
__global__ __launch_bounds__(512) void ln_split(
    const float* __restrict__ in, const float2* __restrict__ stats,
    __nv_bfloat16* __restrict__ ohi, __nv_bfloat16* __restrict__ olo, int per)
{
    const int b = blockIdx.x;
    const float2 st = stats[b];
    const float mean = st.x, inv = st.y;
    const float4* ip = (const float4*)(in + (size_t)b * per);
    uint2* hp = (uint2*)(ohi + (size_t)b * per);
    uint2* lp = (uint2*)(olo + (size_t)b * per);
    const int n4 = per / 4;
    for (int i = threadIdx.x; i < n4; i += 512) {
        float4 v = ip[i];
        float x0 = fmaxf((v.x - mean) * inv, 0.f);
        float x1 = fmaxf((v.y - mean) * inv, 0.f);
        float x2 = fmaxf((v.z - mean) * inv, 0.f);
        float x3 = fmaxf((v.w - mean) * inv, 0.f);
        unsigned short h0, l0, h1, l1, h2, l2, h3, l3;
        split_bf16(x0, h0, l0); split_bf16(x1, h1, l1);
        split_bf16(x2, h2, l2); split_bf16(x3, h3, l3);
        hp[i] = make_uint2((uint32_t)h0 | ((uint32_t)h1 << 16),
                           (uint32_t)h2 | ((uint32_t)h3 << 16));
        lp[i] = make_uint2((uint32_t)l0 | ((uint32_t)l1 << 16),
                           (uint32_t)l2 | ((uint32_t)l3 << 16));
    }
}

// ---------------------------------------------------------------------------
// Conv: 128(M) x 64(O) tile per CTA, 8 warps (4m x 2n, 32x32 warp tiles),
// cp.async depth-2, 96KB dyn smem -> 2 CTAs/SM (hides sync bubbles in the
// quarter-rate HMMA pipe).
// Stage layout: A_hi 0..16K, A_lo 16K..32K, B_hi 32K..40K, B_lo 40K..48K
// ---------------------------------------------------------------------------
#define STG 49152
#define DYN_SMEM (2 * STG)

template<int O, int Cp, bool STATS>
__global__ __launch_bounds__(256, 2) void conv_mma(
    const __nv_bfloat16* __restrict__ Xhi,   // [B][128][Cp]
    const __nv_bfloat16* __restrict__ Xlo,
    const int*   __restrict__ idx,
    const __nv_bfloat16* __restrict__ whi,   // [O][3*Cp]
    const __nv_bfloat16* __restrict__ wlo,
    const float* __restrict__ bias,
    float2* __restrict__ part_out,
    float* __restrict__ out)                 // [B][128][O]
{
    const int KT = 3 * Cp;
    const int NCH = Cp / 64;
    const int NC = 3 * NCH;

    extern __shared__ char base[];
    __shared__ int idxs[384];
    __shared__ float sbias[64];
    __shared__ float redS[8], redS2[8];

    const int b  = blockIdx.y;
    const int o0 = blockIdx.x * 64;
    const int t  = threadIdx.x;
    const int wid = t >> 5, lane = t & 31;

    for (int i = t; i < 384; i += 256) idxs[i] = (i < N3) ? idx[b * N3 + i] : 0;
    if (t < 64) sbias[t] = bias[o0 + t];
    __syncthreads();

    const __nv_bfloat16* XhB = Xhi + (size_t)b * MM * Cp;
    const __nv_bfloat16* XlB = Xlo + (size_t)b * MM * Cp;
    const uint32_t sbase = smem_u32(base);

    auto issue = [&](int ch, int s) {
        const int k3 = ch / NCH, c0 = (ch - k3 * NCH) * 64;
        const uint32_t st = sbase + s * STG;
        // A: 128 rows x 8 parts, hi+lo (gathered; row 127 zero-filled)
        #pragma unroll
        for (int i = 0; i < 4; i++) {
            int e = i * 256 + t, r = e >> 3, part = e & 7;
            uint32_t d = st + SW128(r * 128 + part * 16);
            int sz = (r < 127) ? 16 : 0;
            size_t g = (size_t)idxs[3 * r + k3] * Cp + c0 + part * 8;
            cp_async16(d,         XhB + g, sz);
            cp_async16(d + 16384, XlB + g, sz);
        }
        // B: 64 rows x 8 parts, hi+lo
        #pragma unroll
        for (int i = 0; i < 2; i++) {
            int e = i * 256 + t, r = e >> 3, part = e & 7;
            uint32_t d = st + 32768 + SW128(r * 128 + part * 16);
            size_t g = (size_t)(o0 + r) * KT + k3 * Cp + c0 + part * 8;
            cp_async16(d,        whi + g, 16);
            cp_async16(d + 8192, wlo + g, 16);
        }
        cp_commit();
    };

    const int m0 = (wid & 3) * 32;   // 4 M bands of 32
    const int n0 = (wid >> 2) * 32;  // 2 N bands of 32

    float acc[2][4][4];
    #pragma unroll
    for (int i = 0; i < 2; i++)
        #pragma unroll
        for (int j = 0; j < 4; j++)
            #pragma unroll
            for (int q = 0; q < 4; q++) acc[i][j][q] = 0.f;

    issue(0, 0);
    if (NC > 1) issue(1, 1);

    for (int ch = 0; ch < NC; ch++) {
        const int s = ch & 1;
        if (ch + 1 < NC) cp_wait<1>(); else cp_wait<0>();
        __syncthreads();

        const uint32_t tA_hi = sbase + s * STG;
        const uint32_t tA_lo = tA_hi + 16384;
        const uint32_t tB_hi = tA_hi + 32768;
        const uint32_t tB_lo = tA_hi + 40960;
        #pragma unroll
        for (int ks = 0; ks < 4; ks++) {
            uint32_t ah[2][4], al[2][4];
            const int arow = lane & 15, ahalf = lane >> 4;
            #pragma unroll
            for (int mi = 0; mi < 2; mi++) {
                uint32_t off = SW128((m0 + 16 * mi + arow) * 128 + ks * 32 + ahalf * 16);
                ldmx4(ah[mi], tA_hi + off);
                ldmx4(al[mi], tA_lo + off);
            }
            uint32_t bh[2][4], bl[2][4];
            #pragma unroll
            for (int h = 0; h < 2; h++) {
                uint32_t off = SW128((n0 + lane) * 128 + ks * 32 + h * 16);
                ldmx4(bh[h], tB_hi + off);
                ldmx4(bl[h], tB_lo + off);
            }
            #pragma unroll
            for (int mi = 0; mi < 2; mi++)
                #pragma unroll
                for (int nj = 0; nj < 4; nj++) {
                    mma16816(acc[mi][nj], ah[mi], bh[0][nj], bh[1][nj]);
                    mma16816(acc[mi][nj], ah[mi], bl[0][nj], bl[1][nj]);
                    mma16816(acc[mi][nj], al[mi], bh[0][nj], bh[1][nj]);
                }
        }
        __syncthreads();
        if (ch + 2 < NC) issue(ch + 2, s);
    }

    // ---- epilogue: direct stores (m = r+1, row 0 zeroed) + register stats ----
    float* outB = out + (size_t)b * MM * O + o0;
    if (t < 64) outB[t] = 0.f;

    float s = 0.f, s2 = 0.f;
    #pragma unroll
    for (int mi = 0; mi < 2; mi++) {
        int r_lo = m0 + 16 * mi + (lane >> 2);
        int r_hi = r_lo + 8;
        #pragma unroll
        for (int nj = 0; nj < 4; nj++) {
            int n = n0 + 8 * nj + 2 * (lane & 3);
            float b0 = sbias[n], b1 = sbias[n + 1];
            float v0 = acc[mi][nj][0] + b0, v1 = acc[mi][nj][1] + b1;
            *(float2*)&outB[(size_t)(r_lo + 1) * O + n] = make_float2(v0, v1);
            if (STATS) { s += v0 + v1; s2 += v0 * v0 + v1 * v1; }
            if (r_hi < 127) {
                float v2 = acc[mi][nj][2] + b0, v3 = acc[mi][nj][3] + b1;
                *(float2*)&outB[(size_t)(r_hi + 1) * O + n] = make_float2(v2, v3);
                if (STATS) { s += v2 + v3; s2 += v2 * v2 + v3 * v3; }
            }
        }
    }
    if (STATS) {
        #pragma unroll
        for (int off = 16; off; off >>= 1) {
            s  += __shfl_xor_sync(0xFFFFFFFFu, s,  off);
            s2 += __shfl_xor_sync(0xFFFFFFFFu, s2, off);
        }
        if (lane == 0) { redS[wid] = s; redS2[wid] = s2; }
        __syncthreads();
        if (t == 0) {
            float S = 0.f, S2 = 0.f;
            #pragma unroll
            for (int i = 0; i < 8; i++) { S += redS[i]; S2 += redS2[i]; }
            part_out[b * (O / 64) + blockIdx.x] = make_float2(S, S2);
        }
    }
}

__global__ void finalize_stats(const float2* __restrict__ part, int nOC,
                               float2* __restrict__ stats, float cnt)
{
    int b = blockIdx.x * blockDim.x + threadIdx.x;
    if (b >= BB) return;
    float S = 0.f, S2 = 0.f;
    for (int i = 0; i < nOC; i++) { float2 p = part[b * nOC + i]; S += p.x; S2 += p.y; }
    double mean = (double)S / (double)cnt;
    double var  = ((double)S2 - (double)S * (double)S / (double)cnt) / ((double)cnt - 1.0);
    if (var < 0.0) var = 0.0;
    stats[b] = make_float2((float)mean, 1.f / ((float)sqrt(var) + 1e-5f));
}

// ---------------------------------------------------------------------------
// Attention head + MLP, emb node-major [B][128][256]
// ---------------------------------------------------------------------------
__global__ __launch_bounds__(256) void head_kernel(
    const float* __restrict__ emb,
    const float* __restrict__ gw1, const float* __restrict__ gb1,
    const float* __restrict__ gw2, const float* __restrict__ gb2,
    const float* __restrict__ rw1, const float* __restrict__ rb1,
    const float* __restrict__ rw2, const float* __restrict__ rb2,
    const float* __restrict__ rw3, const float* __restrict__ rb3,
    float* __restrict__ dout, int write_comb, int write_out)
{
    const int b = blockIdx.x;
    const int t = threadIdx.x;
    const float* E = emb + (size_t)b * MM * FF;

    __shared__ __align__(16) float es[128][33];
    __shared__ __align__(16) float gwT[32][132];
    __shared__ float gates[128];
    __shared__ float red[256];
    __shared__ float attn[128];
    __shared__ __align__(16) float comb[512];
    __shared__ float h1s[128];
    __shared__ float h2s[64];

    const int m  = t >> 1;
    const int h0 = (t & 1) * 64;

    float acc[64];
    #pragma unroll
    for (int j = 0; j < 64; j++) acc[j] = 0.f;

    for (int fc = 0; fc < FF; fc += 32) {
        #pragma unroll
        for (int i = 0; i < 16; i++) {
            int e = i * 256 + t;
            es[e >> 5][e & 31] = E[(e >> 5) * FF + fc + (e & 31)];
        }
        #pragma unroll
        for (int i = 0; i < 16; i++) {
            int e = i * 256 + t;
            gwT[e & 31][e >> 5] = gw1[(e >> 5) * FF + fc + (e & 31)];
        }
        __syncthreads();
        #pragma unroll 2
        for (int fl = 0; fl < 32; fl++) {
            float v = es[m][fl];
            const float* gr = &gwT[fl][h0];
            #pragma unroll
            for (int j = 0; j < 64; j++) acc[j] = fmaf(v, gr[j], acc[j]);
        }
        __syncthreads();
    }

    float g2 = 0.f;
    #pragma unroll
    for (int j = 0; j < 64; j++) {
        float g = acc[j] + gb1[h0 + j];
        g2 = fmaf(fmaxf(g, 0.f), gw2[h0 + j], g2);
    }
    red[t] = g2;
    __syncthreads();
    if ((t & 1) == 0) gates[m] = red[t] + red[t + 1] + gb2[0];
    __syncthreads();

    red[t] = (t < 128) ? gates[t] : -3.0e38f;
    __syncthreads();
    for (int off = 128; off > 0; off >>= 1) {
        if (t < off) red[t] = fmaxf(red[t], red[t + off]);
        __syncthreads();
    }
    float mx = red[0];
    __syncthreads();
    float ev = 0.f;
    if (t < 128) { ev = expf(gates[t] - mx); attn[t] = ev; }
    red[t] = (t < 128) ? ev : 0.f;
    __syncthreads();
    for (int off = 128; off > 0; off >>= 1) {
        if (t < off) red[t] += red[t + off];
        __syncthreads();
    }
    float sinv = 1.f / red[0];
    __syncthreads();
    if (t < 128) attn[t] *= sinv;
    __syncthreads();

    {
        const int f = t;
        float pf = 0.f;
        #pragma unroll 4
        for (int mi = 0; mi < 128; mi++)
            pf = fmaf(attn[mi], E[mi * FF + f], pf);
        comb[256 + f] = pf;
        comb[f]       = E[FF + f];
    }
    __syncthreads();

    if (write_comb) {
        dout[512 + (size_t)b * 512 + t]       = comb[t];
        dout[512 + (size_t)b * 512 + 256 + t] = comb[256 + t];
    }

    if (t < 128) {
        const float4* wr = (const float4*)(rw1 + t * 512);
        const float4* cb = (const float4*)comb;
        float a = rb1[t];
        #pragma unroll 8
        for (int q = 0; q < 128; q++) {
            float4 wv = wr[q];
            float4 cv = cb[q];
            a = fmaf(wv.x, cv.x, a);
            a = fmaf(wv.y, cv.y, a);
            a = fmaf(wv.z, cv.z, a);
            a = fmaf(wv.w, cv.w, a);
        }
        h1s[t] = fmaxf(a, 0.f);
    }
    __syncthreads();
    if (t < 64) {
        const float* wr = rw2 + t * 128;
        float a = rb2[t];
        #pragma unroll 4
        for (int i = 0; i < 128; i++) a = fmaf(h1s[i], wr[i], a);
        h2s[t] = fmaxf(a, 0.f);
    }
    __syncthreads();
    red[t] = (t < 64) ? h2s[t] * rw3[t] : 0.f;
    __syncthreads();
    for (int off = 32; off > 0; off >>= 1) {
        if (t < off) red[t] += red[t + off];
        __syncthreads();
    }
    if (t == 0 && write_out) dout[b] = red[0] + rb3[0];
}

// ---------------------------------------------------------------------------
extern "C" void kernel_launch(void* const* d_in, const int* in_sizes, int n_in,
                              void* d_out, int out_size)
{
    const float* trees   = (const float*)d_in[0];
    const int*   indexes = (const int*)  d_in[1];
    const float* w1  = (const float*)d_in[2];
    const float* b1  = (const float*)d_in[3];
    const float* w2  = (const float*)d_in[4];
    const float* b2  = (const float*)d_in[5];
    const float* w3  = (const float*)d_in[6];
    const float* b3  = (const float*)d_in[7];
    const float* gw1 = (const float*)d_in[8];
    const float* gb1 = (const float*)d_in[9];
    const float* gw2 = (const float*)d_in[10];
    const float* gb2 = (const float*)d_in[11];
    const float* rw1 = (const float*)d_in[12];
    const float* rb1 = (const float*)d_in[13];
    const float* rw2 = (const float*)d_in[14];
    const float* rb2 = (const float*)d_in[15];
    const float* rw3 = (const float*)d_in[16];
    const float* rb3 = (const float*)d_in[17];
    float* out = (float*)d_out;

    float *buf1, *buf2;
    __nv_bfloat16 *tHi, *tLo, *aHi, *aLo;
    __nv_bfloat16 *w1h, *w1l, *w2h, *w2l, *w3h, *w3l;
    float2 *part, *st1, *st2;
    cudaGetSymbolAddress((void**)&buf1, g_buf1);
    cudaGetSymbolAddress((void**)&buf2, g_buf2);
    cudaGetSymbolAddress((void**)&tHi, g_tHi);
    cudaGetSymbolAddress((void**)&tLo, g_tLo);
    cudaGetSymbolAddress((void**)&aHi, g_aHi);
    cudaGetSymbolAddress((void**)&aLo, g_aLo);
    cudaGetSymbolAddress((void**)&w1h, g_w1_hi);
    cudaGetSymbolAddress((void**)&w1l, g_w1_lo);
    cudaGetSymbolAddress((void**)&w2h, g_w2_hi);
    cudaGetSymbolAddress((void**)&w2l, g_w2_lo);
    cudaGetSymbolAddress((void**)&w3h, g_w3_hi);
    cudaGetSymbolAddress((void**)&w3l, g_w3_lo);
    cudaGetSymbolAddress((void**)&part, g_part);
    cudaGetSymbolAddress((void**)&st1, g_stats1);
    cudaGetSymbolAddress((void**)&st2, g_stats2);

    cudaFuncSetAttribute(conv_mma<H1, CP1, true>,
                         cudaFuncAttributeMaxDynamicSharedMemorySize, DYN_SMEM);
    cudaFuncSetAttribute(conv_mma<H2, H1, true>,
                         cudaFuncAttributeMaxDynamicSharedMemorySize, DYN_SMEM);
    cudaFuncSetAttribute(conv_mma<FF, H2, false>,
                         cudaFuncAttributeMaxDynamicSharedMemorySize, DYN_SMEM);

    const long long need_comb = 512LL + (long long)BB * 512LL;
    int write_comb = ((long long)out_size >= need_comb) ? 1 : 0;
    int write_out  = (out_size >= BB) ? 1 : 0;

    transpose_split<<<dim3(CP1 / 32, MM / 32, BB), 256>>>(trees, tHi, tLo);
    wprep<<<(H1 * 3 * CP1 + 255) / 256, 256>>>(w1, w1h, w1l, H1, CIN, CP1);
    wprep<<<(H2 * 3 * H1 + 255) / 256, 256>>>(w2, w2h, w2l, H2, H1, H1);
    wprep<<<(FF * 3 * H2 + 255) / 256, 256>>>(w3, w3h, w3l, FF, H2, H2);

    conv_mma<H1, CP1, true><<<dim3(H1 / 64, BB), 256, DYN_SMEM>>>(
        tHi, tLo, indexes, w1h, w1l, b1, part, buf1);
    finalize_stats<<<(BB + 127) / 128, 128>>>(part, H1 / 64, st1, (float)(H1 * MM));
    ln_split<<<BB, 512>>>(buf1, st1, aHi, aLo, MM * H1);

    conv_mma<H2, H1, true><<<dim3(H2 / 64, BB), 256, DYN_SMEM>>>(
        aHi, aLo, indexes, w2h, w2l, b2, part, buf2);
    finalize_stats<<<(BB + 127) / 128, 128>>>(part, H2 / 64, st2, (float)(H2 * MM));
    ln_split<<<BB, 512>>>(buf2, st2, aHi, aLo, MM * H2);

    conv_mma<FF, H2, false><<<dim3(FF / 64, BB), 256, DYN_SMEM>>>(
        aHi, aLo, indexes, w3h, w3l, b3, nullptr, buf1);

    head_kernel<<<BB, 256>>>(buf1, gw1, gb1, gw2, gb2,
                             rw1, rb1, rw2, rb2, rw3, rb3, out,
                             write_comb, write_out);
}